// round 16
// baseline (speedup 1.0000x reference)
#include <cuda_runtime.h>
#include <cuda_bf16.h>
#include <cstdint>

#define NSPAN  256
#define KKNOW  1024
#define DMODEL 512
#define LMAX   64
#define HID    500
#define NPAIR  (NSPAN * (LMAX + 1))   /* 16640 = 130 * 128 */

// ---------------- scratch (device globals; no allocation) ----------------
__device__ float    g_sentinel[NSPAN * DMODEL];   // fp32 (softmax needs it)
__device__ uint32_t g_span_b[NSPAN * 256];        // span_part bf16x2, PERMW
__device__ uint32_t g_know_b[KKNOW * 256];        // know_part bf16x2, PERMW
__device__ uint32_t g_sent_b[NSPAN * 256];        // sent_part bf16x2, PERMW
__device__ uint32_t g_W2b[DMODEL * 256];          // W2^T  bf16x2, PERMW
__device__ uint32_t g_Wsb[DMODEL * 256];          // Ws^T  bf16x2
__device__ uint32_t g_W1ab[DMODEL * 256];         // W1a^T bf16x2
__device__ uint32_t g_W1bb[DMODEL * 256];         // W1b^T bf16x2
__device__ float g_b2p[DMODEL];
__device__ float g_w3p[DMODEL];
__device__ float g_scpart[4 * NPAIR];             // per-N-tile score partials
__device__ int g_sentflag;                        // sentinel-done counter
__device__ int g_scnt[NSPAN];                     // per-span completion counters

__device__ __forceinline__ uint32_t packbf(float lo, float hi) {
    uint32_t r;
    asm("cvt.rn.bf16x2.f32 %0, %1, %2;" : "=r"(r) : "f"(hi), "f"(lo));
    return r;
}
__device__ __forceinline__ uint32_t addrelu_bf2(uint32_t a, uint32_t b) {
    __nv_bfloat162 x = __hadd2(*(__nv_bfloat162*)&a, *(__nv_bfloat162*)&b);
    __nv_bfloat162 z = __float2bfloat162_rn(0.f);
    x = __hmax2(x, z);
    return *(uint32_t*)&x;
}
__device__ __forceinline__ uint32_t smem_u32(const void* p) {
    uint32_t a;
    asm("{ .reg .u64 t; cvta.to.shared.u64 t, %1; cvt.u32.u64 %0, t; }"
        : "=r"(a) : "l"(p));
    return a;
}
__device__ __forceinline__ void mma_bf16(float* c,
                                         uint32_t a0, uint32_t a1, uint32_t a2, uint32_t a3,
                                         uint32_t b0, uint32_t b1) {
    asm volatile(
        "mma.sync.aligned.m16n8k16.row.col.f32.bf16.bf16.f32 "
        "{%0,%1,%2,%3}, {%4,%5,%6,%7}, {%8,%9}, {%0,%1,%2,%3};"
        : "+f"(c[0]), "+f"(c[1]), "+f"(c[2]), "+f"(c[3])
        : "r"(a0), "r"(a1), "r"(a2), "r"(a3), "r"(b0), "r"(b1));
}
#define CP_ASYNC16(dst, src) \
    asm volatile("cp.async.cg.shared.global [%0], [%1], 16;" \
                 :: "r"(dst), "l"(src) : "memory")
#define CP_COMMIT() asm volatile("cp.async.commit_group;" ::: "memory")
#define CP_WAIT(n)  asm volatile("cp.async.wait_group %0;" :: "n"(n) : "memory")

// word-pair permutation: pair g (cols 2g,2g+1) stored at (g&~7)+PERMW(g&7)
#define PERMW(w) ((((w) & 3) << 1) | (((w) >> 2) & 1))

// smem layout (words): A 2x1024 @0, B 4x1024 @2048, sred 256 @6144,
// softmax scratch @6400: sc 65, flags 4, rmax/rinv; eptr 72 ptr slots @6528
#define SMEM_BYTES ((6528 + 160) * 4)

// ---------------- prep: smem tile transpose, coalesced both sides ----------
// grid (64, 4): 8x8 tiles of 64(n) x 64(k) per matrix; 256 threads.
__global__ void __launch_bounds__(256) prep_kernel(
    const float* __restrict__ W2, const float* __restrict__ Ws,
    const float* __restrict__ W1, const float* __restrict__ b2,
    const float* __restrict__ W3) {
    __shared__ float ts[64][65];
    const int z = blockIdx.y;
    const int tile = blockIdx.x;
    const int tn = (tile & 7) * 64;
    const int tk = (tile >> 3) * 64;
    const int tid = threadIdx.x;

    if (z == 0 && tile == 0 && tid == 0) g_sentflag = 0;
    if (z == 1 && tile == 0) g_scnt[tid] = 0;     // reset span counters
    if (z == 1 && tile == 1) g_scnt[tid] = 0;     // (redundant safe clear)
    if (z == 0 && tile < 2) {
        int i = tile * 256 + tid;
        g_b2p[i] = (i < HID) ? b2[i] : 0.f;
        g_w3p[i] = (i < HID) ? W3[i] : 0.f;
    }

    const int nl = tid & 63;
    const int kb = tid >> 6;                 // 0..3
    const int n = tn + nl;
#pragma unroll
    for (int i = 0; i < 16; i++) {
        int kl = kb * 16 + i;
        int k = tk + kl;
        float v;
        if (z == 0)      v = (k < HID && n < HID) ? W2[k * HID + n] : 0.f;
        else if (z == 1) v = Ws[k * DMODEL + n];
        else if (z == 2) v = (n < HID) ? W1[k * HID + n] : 0.f;
        else             v = (n < HID) ? W1[(k + DMODEL) * HID + n] : 0.f;
        ts[kl][nl] = v;
    }
    __syncthreads();

    uint32_t* dst = (z == 0) ? g_W2b : (z == 1) ? g_Wsb : (z == 2) ? g_W1ab : g_W1bb;
    const int wn = tid >> 2;                 // local n (0..63)
    const int gblk = tid & 3;                // 8-word group (0..3)
    uint32_t wbuf[8];
#pragma unroll
    for (int j = 0; j < 8; j++) {
        int kk = (gblk * 8 + j) * 2;
        wbuf[PERMW(j)] = packbf(ts[kk][wn], ts[kk + 1][wn]);
    }
    uint32_t* o = dst + (size_t)(tn + wn) * 256 + tk / 2 + gblk * 8;
    *(uint4*)&o[0] = *(uint4*)&wbuf[0];
    *(uint4*)&o[4] = *(uint4*)&wbuf[4];
}

// ================= unified bf16 pipelined GEMM core =================
// CTA 128(M) x 128(N), K=512 in 32 chunks of 16. 8 warps (4M x 2N), 32x64.
// MODE 0: fp32 A -> fp32 C (+bias/relu)            [sentinel]
// MODE 1: fp32 A -> bf16x2 permuted C (+bias)      [parts]
// MODE 2: bf16 A pair (add+relu) -> score partials [pair]
template<int MODE>
__device__ __forceinline__ void gemm_core(
    int m0, int n0,
    const float* __restrict__ arpF,
    const uint4* __restrict__ arpA, const uint4* __restrict__ arpB,
    const uint32_t* __restrict__ Btw,
    const float* __restrict__ bias, void* Cout, int N, int relu) {
    extern __shared__ uint32_t sm[];
    const int tid = threadIdx.x;
    const int lane = tid & 31, wid = tid >> 5;
    const int gid = lane >> 2, tig = lane & 3;
    const int wm = wid >> 1, wn = wid & 1;
    const int row = tid >> 1, ah = tid & 1;

    const char* brp = (const char*)Btw + (size_t)(n0 + row) * 1024 + ah * 16;

    uint32_t su = smem_u32(sm);
    uint32_t bdst[4];
#pragma unroll
    for (int q = 0; q < 4; q++)
        bdst[q] = su + (uint32_t)(2048 + q * 1024 + row * 8 + ah * 4) * 4;

    float acc[2][8][4];
#pragma unroll
    for (int mi = 0; mi < 2; mi++)
#pragma unroll
        for (int ni = 0; ni < 8; ni++)
#pragma unroll
            for (int q = 0; q < 4; q++) acc[mi][ni][q] = 0.f;

    float4 pa1[2];
    uint4 ua1, ua2;

#define LDA(s) do {                                                           \
    if (MODE == 2) {                                                          \
        ua1 = arpA[(s) * 2 + ah];                                             \
        ua2 = arpB[(s) * 2 + ah];                                             \
    } else {                                                                  \
        int _k = (s) * 16;                                                    \
        pa1[0] = *(const float4*)(arpF + _k);                                 \
        pa1[1] = *(const float4*)(arpF + _k + 8);                             \
    } } while (0)

#define STA(b) do {                                                           \
    uint4 q;                                                                  \
    if (MODE == 2) {                                                          \
        q.x = addrelu_bf2(ua1.x, ua2.x);                                      \
        q.y = addrelu_bf2(ua1.y, ua2.y);                                      \
        q.z = addrelu_bf2(ua1.z, ua2.z);                                      \
        q.w = addrelu_bf2(ua1.w, ua2.w);                                      \
    } else {                                                                  \
        q = make_uint4(packbf(pa1[0].x, pa1[0].y), packbf(pa1[1].x, pa1[1].y),\
                       packbf(pa1[0].z, pa1[0].w), packbf(pa1[1].z, pa1[1].w));\
    }                                                                         \
    *(uint4*)&sm[(b) * 1024 + row * 8 + ah * 4] = q; } while (0)

#define LDB(s, q) do { if ((s) < 32)                                          \
        CP_ASYNC16(bdst[q], brp + (s) * 32);                                  \
    CP_COMMIT(); } while (0)

#define COMPUTE(AB, BB) do {                                                  \
    const uint32_t* A_ = sm + (AB) * 1024;                                    \
    const uint32_t* B_ = sm + 2048 + (BB) * 1024;                             \
    uint2 bfr[8];                                                             \
    _Pragma("unroll") for (int ni = 0; ni < 8; ni++) {                        \
        int nr = wn * 64 + ni * 8 + gid;                                      \
        bfr[ni] = *(const uint2*)&B_[nr * 8 + tig * 2];                       \
    }                                                                         \
    _Pragma("unroll") for (int mi = 0; mi < 2; mi++) {                        \
        int r = wm * 32 + mi * 16 + gid;                                      \
        uint2 u0 = *(const uint2*)&A_[r * 8 + tig * 2];                       \
        uint2 u1 = *(const uint2*)&A_[(r + 8) * 8 + tig * 2];                 \
        _Pragma("unroll") for (int ni = 0; ni < 8; ni++)                      \
            mma_bf16(acc[mi][ni], u0.x, u1.x, u0.y, u1.y,                     \
                     bfr[ni].x, bfr[ni].y);                                   \
    } } while (0)

#define ITER(s, AB, BB) do {                                                  \
    if ((s) + 1 < 32) STA((AB) ^ 1);                                          \
    if ((s) + 2 < 32) LDA((s) + 2);                                           \
    LDB((s) + 3, ((BB) + 3) & 3);                                             \
    CP_WAIT(2);                                                               \
    COMPUTE(AB, BB);                                                          \
    __syncthreads(); } while (0)

    LDA(0); STA(0);
    LDB(0, 0); LDB(1, 1); LDB(2, 2);
    LDA(1);
    CP_WAIT(2);
    __syncthreads();

#pragma unroll 1
    for (int s0 = 0; s0 < 28; s0 += 4) {
        ITER(s0 + 0, 0, 0);
        ITER(s0 + 1, 1, 1);
        ITER(s0 + 2, 0, 2);
        ITER(s0 + 3, 1, 3);
    }
    ITER(28, 0, 0);
    ITER(29, 1, 1);
    ITER(30, 0, 2);
    ITER(31, 1, 3);

#undef LDA
#undef STA
#undef LDB
#undef COMPUTE
#undef ITER

    if (MODE == 2) {
        float* sred = (float*)(sm + 6144);
#pragma unroll
        for (int mi = 0; mi < 2; mi++) {
            float p0 = 0.f, p1 = 0.f;
#pragma unroll
            for (int ni = 0; ni < 8; ni++) {
                int nn = n0 + wn * 64 + ni * 8 + 2 * tig;
                float b2a = g_b2p[nn],     w3a = g_w3p[nn];
                float b2b = g_b2p[nn + 1], w3b = g_w3p[nn + 1];
                p0 += fmaxf(acc[mi][ni][0] + b2a, 0.f) * w3a
                    + fmaxf(acc[mi][ni][1] + b2b, 0.f) * w3b;
                p1 += fmaxf(acc[mi][ni][2] + b2a, 0.f) * w3a
                    + fmaxf(acc[mi][ni][3] + b2b, 0.f) * w3b;
            }
            p0 += __shfl_xor_sync(0xFFFFFFFFu, p0, 1);
            p0 += __shfl_xor_sync(0xFFFFFFFFu, p0, 2);
            p1 += __shfl_xor_sync(0xFFFFFFFFu, p1, 1);
            p1 += __shfl_xor_sync(0xFFFFFFFFu, p1, 2);
            if (tig == 0) {
                int r = wm * 32 + mi * 16 + gid;
                sred[r * 2 + wn] = p0;
                sred[(r + 8) * 2 + wn] = p1;
            }
        }
        __syncthreads();
        if (tid < 128) {
            g_scpart[blockIdx.x * NPAIR + m0 + tid] = sred[tid * 2] + sred[tid * 2 + 1];
            __threadfence();   // push scpart to L2 before completion signal
        }
    } else if (MODE == 1) {
        uint32_t* Cw = (uint32_t*)Cout;
#pragma unroll
        for (int mi = 0; mi < 2; mi++) {
            int r = m0 + wm * 32 + mi * 16 + gid;
#pragma unroll
            for (int ni = 0; ni < 8; ni++) {
                int nn = n0 + wn * 64 + ni * 8 + 2 * tig;
                float ba = (bias && nn < N) ? bias[nn] : 0.f;
                float bb = (bias && nn + 1 < N) ? bias[nn + 1] : 0.f;
                float c0 = (nn < N) ? acc[mi][ni][0] + ba : 0.f;
                float c1 = (nn + 1 < N) ? acc[mi][ni][1] + bb : 0.f;
                float c2 = (nn < N) ? acc[mi][ni][2] + ba : 0.f;
                float c3 = (nn + 1 < N) ? acc[mi][ni][3] + bb : 0.f;
                int g = nn >> 1;
                int pos = (g & ~7) + PERMW(g & 7);
                Cw[(size_t)r * 256 + pos] = packbf(c0, c1);
                Cw[(size_t)(r + 8) * 256 + pos] = packbf(c2, c3);
            }
        }
    } else {
        float* C = (float*)Cout;
#pragma unroll
        for (int mi = 0; mi < 2; mi++) {
            int r = m0 + wm * 32 + mi * 16 + gid;
#pragma unroll
            for (int ni = 0; ni < 8; ni++) {
                int nn = n0 + wn * 64 + ni * 8 + 2 * tig;
                float ba = (bias && nn < N) ? bias[nn] : 0.f;
                float bb = (bias && nn + 1 < N) ? bias[nn + 1] : 0.f;
                float c0 = (nn < N) ? acc[mi][ni][0] + ba : 0.f;
                float c1 = (nn + 1 < N) ? acc[mi][ni][1] + bb : 0.f;
                float c2 = (nn < N) ? acc[mi][ni][2] + ba : 0.f;
                float c3 = (nn + 1 < N) ? acc[mi][ni][3] + bb : 0.f;
                if (relu) {
                    c0 = fmaxf(c0, 0.f); c1 = fmaxf(c1, 0.f);
                    c2 = fmaxf(c2, 0.f); c3 = fmaxf(c3, 0.f);
                }
                *(float2*)&C[(size_t)r * DMODEL + nn] = make_float2(c0, c1);
                *(float2*)&C[(size_t)(r + 8) * DMODEL + nn] = make_float2(c2, c3);
            }
        }
    }
}

// ---------------- inline softmax + features for one span (256 threads) -----
__device__ void span_softmax(int n, const int* __restrict__ s2c,
                             const int* __restrict__ lengths,
                             const float* __restrict__ know,
                             float* __restrict__ out) {
    extern __shared__ uint32_t sm[];
    float* sc = (float*)(sm + 6400);                 // 65 floats
    float* rr = (float*)(sm + 6472);                 // rmax, rinv
    const float** eptr = (const float**)(sm + 6528); // 65 pointers
    int t = threadIdx.x;

    if (t < 65) {
        // scpart written by other CTAs: bypass L1
        float s = __ldcg(&g_scpart[0 * NPAIR + n * 65 + t])
                + __ldcg(&g_scpart[1 * NPAIR + n * 65 + t])
                + __ldcg(&g_scpart[2 * NPAIR + n * 65 + t])
                + __ldcg(&g_scpart[3 * NPAIR + n * 65 + t]);
        bool valid;
        const float* ep;
        if (t < LMAX) {
            int len = lengths[n];
            if (len < 1) len = 1;
            valid = t < len;
            ep = know + (size_t)s2c[n * LMAX + t] * DMODEL;
        } else {
            valid = true;
            ep = g_sentinel + (size_t)n * DMODEL;
        }
        sc[t] = valid ? s : -1e30f;
        eptr[t] = ep;
    }
    __syncthreads();
    if (t < 32) {
        float v = fmaxf(sc[t], sc[t + 32]);
        if (t == 0) v = fmaxf(v, sc[64]);
#pragma unroll
        for (int o = 16; o; o >>= 1)
            v = fmaxf(v, __shfl_xor_sync(0xFFFFFFFFu, v, o));
        if (t == 0) rr[0] = v;
    }
    __syncthreads();
    float m = rr[0];
    if (t < 65) sc[t] = expf(sc[t] - m);
    __syncthreads();
    if (t < 32) {
        float v = sc[t] + sc[t + 32];
        if (t == 0) v += sc[64];
#pragma unroll
        for (int o = 16; o; o >>= 1)
            v += __shfl_xor_sync(0xFFFFFFFFu, v, o);
        if (t == 0) rr[1] = 1.f / v;
    }
    __syncthreads();
    float inv = rr[1];
    if (t < 65) {
        sc[t] *= inv;
        out[NSPAN * DMODEL + n * 65 + t] = sc[t];    // probs
    }
    __syncthreads();
    // features: 256 threads x 2 dims each (float2, coalesced)
    float a0 = 0.f, a1 = 0.f;
#pragma unroll 5
    for (int l = 0; l < 65; l++) {
        float pr = sc[l];
        float2 e = *(const float2*)&eptr[l][2 * t];
        a0 += pr * e.x;
        a1 += pr * e.y;
    }
    *(float2*)&out[n * DMODEL + 2 * t] = make_float2(a0, a1);
    __syncthreads();   // protect smem reuse across spans
}

// ---------------- pair GEMM + inline last-CTA softmax ----------------
__global__ void __launch_bounds__(256, 2) pair_mma_kernel(
    const int* __restrict__ s2c, const int* __restrict__ lengths,
    const float* __restrict__ know, float* __restrict__ out) {
    extern __shared__ uint32_t sm[];
    const int m0 = blockIdx.y * 128;
    const int row = threadIdx.x >> 1;
    int p = m0 + row, nsp = p / 65, l = p - nsp * 65;
    const uint4* a1 = (const uint4*)(g_span_b + (size_t)nsp * 256);
    const uint4* a2 = (l < LMAX)
        ? (const uint4*)(g_know_b + (size_t)s2c[nsp * LMAX + l] * 256)
        : (const uint4*)(g_sent_b + (size_t)nsp * 256);
    gemm_core<2>(m0, blockIdx.x * 128, nullptr, a1, a2, g_W2b,
                 nullptr, nullptr, 0, 0);

    // ---- per-span completion: last contributing CTA runs softmax ----
    int* flags = (int*)(sm + 6480);                  // up to 4 span slots
    // spans overlapping rows [m0, m0+127]
    int s_min = (m0 - 64 + 64) / 65;                 // ceil((m0-64)/65) for m0>=64
    if (m0 >= 64) s_min = (m0 - 64 + 64) / 65;       // = (m0)/65 approx; compute exactly below
    s_min = (m0 <= 64) ? 0 : (m0 - 64 + 64) / 65;    // ceil((m0-64)/65)
    {
        int a = m0 - 64;
        s_min = (a <= 0) ? 0 : (a + 64) / 65;
    }
    int s_max = (m0 + 127) / 65;
    if (s_max > NSPAN - 1) s_max = NSPAN - 1;

    __syncthreads();                                 // all scpart stores+fences done
    if (threadIdx.x == 0) {
        int idx = 0;
        for (int s = s_min; s <= s_max; s++) {
            int t_lo = (s * 65) / 128;
            int t_hi = (s * 65 + 64) / 128;
            int target = 4 * (t_hi - t_lo + 1);
            int old = atomicAdd(&g_scnt[s], 1);
            flags[idx++] = (old == target - 1) ? s : -1;
        }
        for (; idx < 4; idx++) flags[idx] = -1;
    }
    __syncthreads();
    __threadfence();                                 // acquire: see others' scpart
#pragma unroll
    for (int i = 0; i < 4; i++) {
        int s = flags[i];
        if (s >= 0) span_softmax(s, s2c, lengths, know, out);
    }
}

// compact 56-CTA launch: [0,8) sentinel, [8,16) span_part, [16,48) know_part,
// [48,56) sent_part (waits on sentinel via flag).
__global__ void __launch_bounds__(256, 2) small_multi_kernel(
    const float* __restrict__ span, const float* __restrict__ know,
    const float* __restrict__ bs, const float* __restrict__ b1) {
    const int bid = blockIdx.x;
    const int row = threadIdx.x >> 1, ah = threadIdx.x & 1;
    if (bid < 8) {
        int q = bid;
        int m0 = (q >> 2) * 128, n0 = (q & 3) * 128;
        const float* a = span + (size_t)(m0 + row) * DMODEL + ah * 4;
        gemm_core<0>(m0, n0, a, nullptr, nullptr, g_Wsb, bs, g_sentinel, DMODEL, 1);
        __syncthreads();
        if (threadIdx.x == 0) { __threadfence(); atomicAdd(&g_sentflag, 1); }
    } else if (bid < 16) {
        int q = bid - 8;
        int m0 = (q >> 2) * 128, n0 = (q & 3) * 128;
        const float* a = span + (size_t)(m0 + row) * DMODEL + ah * 4;
        gemm_core<1>(m0, n0, a, nullptr, nullptr, g_W1ab, b1, g_span_b, HID, 0);
    } else if (bid < 48) {
        int q = bid - 16;
        int m0 = (q >> 2) * 128, n0 = (q & 3) * 128;
        const float* a = know + (size_t)(m0 + row) * DMODEL + ah * 4;
        gemm_core<1>(m0, n0, a, nullptr, nullptr, g_W1bb, nullptr, g_know_b, HID, 0);
    } else {
        int q = bid - 48;
        int m0 = (q >> 2) * 128, n0 = (q & 3) * 128;
        if (threadIdx.x == 0) {
            while (atomicAdd(&g_sentflag, 0) < 8) __nanosleep(64);
        }
        __syncthreads();
        const float* a = g_sentinel + (size_t)(m0 + row) * DMODEL + ah * 4;
        gemm_core<1>(m0, n0, a, nullptr, nullptr, g_W1bb, nullptr, g_sent_b, HID, 0);
    }
}

// ---------------- launch ----------------
extern "C" void kernel_launch(void* const* d_in, const int* in_sizes, int n_in,
                              void* d_out, int out_size) {
    const float* span    = (const float*)d_in[0];
    const float* know    = (const float*)d_in[1];
    const int*   s2c     = (const int*)d_in[2];
    const int*   lengths = (const int*)d_in[3];
    const float* Ws      = (const float*)d_in[4];
    const float* bs      = (const float*)d_in[5];
    const float* W1      = (const float*)d_in[6];
    const float* b1      = (const float*)d_in[7];
    const float* W2      = (const float*)d_in[8];
    const float* b2      = (const float*)d_in[9];
    const float* W3      = (const float*)d_in[10];
    // d_in[11] = b3: softmax-invariant constant shift, intentionally unused.
    float* out = (float*)d_out;

    cudaFuncSetAttribute(small_multi_kernel,
                         cudaFuncAttributeMaxDynamicSharedMemorySize, SMEM_BYTES);
    cudaFuncSetAttribute(pair_mma_kernel,
                         cudaFuncAttributeMaxDynamicSharedMemorySize, SMEM_BYTES);

    // weights -> bf16x2 permuted (tiled transpose); pad b2/w3; reset flags
    prep_kernel<<<dim3(64, 4), 256>>>(W2, Ws, W1, b2, W3);
    // sentinel / span_part / know_part / sent_part in ONE compact launch
    small_multi_kernel<<<56, 256, SMEM_BYTES>>>(span, know, bs, b1);
    // pair GEMM -> scores -> (last-CTA) softmax + features, fused
    pair_mma_kernel<<<dim3(4, 130), 256, SMEM_BYTES>>>(s2c, lengths, know, out);
}

// round 17
// speedup vs baseline: 1.1429x; 1.1429x over previous
#include <cuda_runtime.h>
#include <cuda_bf16.h>
#include <cstdint>

#define NSPAN  256
#define KKNOW  1024
#define DMODEL 512
#define LMAX   64
#define HID    500
#define NPAIR  (NSPAN * (LMAX + 1))   /* 16640 = 130 * 128 */

// ---------------- scratch (device globals; no allocation) ----------------
__device__ float    g_sentinel[NSPAN * DMODEL];   // fp32 (softmax needs it)
__device__ uint32_t g_span_b[NSPAN * 256];        // span_part bf16x2, PERMW
__device__ uint32_t g_know_b[KKNOW * 256];        // know_part bf16x2, PERMW
__device__ uint32_t g_sent_b[NSPAN * 256];        // sent_part bf16x2, PERMW
__device__ uint32_t g_W2b[DMODEL * 256];          // W2^T  bf16x2, PERMW
__device__ uint32_t g_Wsb[DMODEL * 256];          // Ws^T  bf16x2
__device__ uint32_t g_W1ab[DMODEL * 256];         // W1a^T bf16x2
__device__ uint32_t g_W1bb[DMODEL * 256];         // W1b^T bf16x2
__device__ float g_b2p[DMODEL];
__device__ float g_w3p[DMODEL];
__device__ float g_scpart[4 * NPAIR];             // per-N-tile score partials
__device__ int g_sentflag;                        // sentinel-done counter

__device__ __forceinline__ uint32_t packbf(float lo, float hi) {
    uint32_t r;
    asm("cvt.rn.bf16x2.f32 %0, %1, %2;" : "=r"(r) : "f"(hi), "f"(lo));
    return r;
}
__device__ __forceinline__ uint32_t addrelu_bf2(uint32_t a, uint32_t b) {
    __nv_bfloat162 x = __hadd2(*(__nv_bfloat162*)&a, *(__nv_bfloat162*)&b);
    __nv_bfloat162 z = __float2bfloat162_rn(0.f);
    x = __hmax2(x, z);
    return *(uint32_t*)&x;
}
__device__ __forceinline__ uint32_t smem_u32(const void* p) {
    uint32_t a;
    asm("{ .reg .u64 t; cvta.to.shared.u64 t, %1; cvt.u32.u64 %0, t; }"
        : "=r"(a) : "l"(p));
    return a;
}
__device__ __forceinline__ void mma_bf16(float* c,
                                         uint32_t a0, uint32_t a1, uint32_t a2, uint32_t a3,
                                         uint32_t b0, uint32_t b1) {
    asm volatile(
        "mma.sync.aligned.m16n8k16.row.col.f32.bf16.bf16.f32 "
        "{%0,%1,%2,%3}, {%4,%5,%6,%7}, {%8,%9}, {%0,%1,%2,%3};"
        : "+f"(c[0]), "+f"(c[1]), "+f"(c[2]), "+f"(c[3])
        : "r"(a0), "r"(a1), "r"(a2), "r"(a3), "r"(b0), "r"(b1));
}
#define CP_ASYNC16(dst, src) \
    asm volatile("cp.async.cg.shared.global [%0], [%1], 16;" \
                 :: "r"(dst), "l"(src) : "memory")
#define CP_COMMIT() asm volatile("cp.async.commit_group;" ::: "memory")
#define CP_WAIT(n)  asm volatile("cp.async.wait_group %0;" :: "n"(n) : "memory")

// word-pair permutation: pair g (cols 2g,2g+1) stored at (g&~7)+PERMW(g&7)
#define PERMW(w) ((((w) & 3) << 1) | (((w) >> 2) & 1))

// smem layout (words): A 2x1024 @0, B 4x1024 @2048, sred 256 @6144
#define SMEM_BYTES ((6144 + 256) * 4)

// ---------------- prep v3: 64n x 32k tiles, high-parallelism transpose -----
// grid (128, 4): 8 n-tiles x 16 k-tiles per matrix; 256 threads, 8.3KB smem.
__global__ void __launch_bounds__(256) prep_kernel(
    const float* __restrict__ W2, const float* __restrict__ Ws,
    const float* __restrict__ W1, const float* __restrict__ b2,
    const float* __restrict__ W3) {
    __shared__ float ts[32][65];
    const int z = blockIdx.y;
    const int tile = blockIdx.x;
    const int tn = (tile & 7) * 64;
    const int tk = (tile >> 3) * 32;
    const int tid = threadIdx.x;

    if (z == 0 && tile == 0 && tid == 0) g_sentflag = 0;
    if (z == 0 && tile < 2) {
        int i = tile * 256 + tid;
        g_b2p[i] = (i < HID) ? b2[i] : 0.f;
        g_w3p[i] = (i < HID) ? W3[i] : 0.f;
    }

    // coalesced read: 8 independent 256B row-chunks per thread
#pragma unroll
    for (int i = 0; i < 8; i++) {
        int idx = tid + i * 256;
        int kl = idx >> 6;               // 0..31
        int nl = idx & 63;
        int k = tk + kl, n = tn + nl;
        float v;
        if (z == 0)      v = (k < HID && n < HID) ? W2[k * HID + n] : 0.f;
        else if (z == 1) v = Ws[k * DMODEL + n];
        else if (z == 2) v = (n < HID) ? W1[k * HID + n] : 0.f;
        else             v = (n < HID) ? W1[(k + DMODEL) * HID + n] : 0.f;
        ts[kl][nl] = v;
    }
    __syncthreads();

    uint32_t* dst = (z == 0) ? g_W2b : (z == 1) ? g_Wsb : (z == 2) ? g_W1ab : g_W1bb;
    const int n = tid >> 2;              // local n (0..63)
    const int q = tid & 3;
    const int gh = q >> 1, h = q & 1;    // 8-word group (0..1), half (0..1)
    uint32_t w[4];
#pragma unroll
    for (int s4 = 0; s4 < 4; s4++) {
        int s = h * 4 + s4;              // permuted slot 0..7
        int j = ((s & 1) << 2) | (s >> 1);  // PERMW inverse
        int kl = gh * 16 + 2 * j;
        w[s4] = packbf(ts[kl][n], ts[kl + 1][n]);
    }
    uint32_t* o = dst + (size_t)(tn + n) * 256 + tk / 2 + gh * 8 + h * 4;
    *(uint4*)o = *(uint4*)w;
}

// ================= unified bf16 pipelined GEMM core =================
// CTA 128(M) x 128(N), K=512 in 32 chunks of 16. 8 warps (4M x 2N), 32x64.
// MODE 0: fp32 A -> fp32 C (+bias/relu)            [sentinel]
// MODE 1: fp32 A -> bf16x2 permuted C (+bias)      [parts]
// MODE 2: bf16 A pair (add+relu) -> score partials [pair]
template<int MODE>
__device__ __forceinline__ void gemm_core(
    int m0, int n0,
    const float* __restrict__ arpF,
    const uint4* __restrict__ arpA, const uint4* __restrict__ arpB,
    const uint32_t* __restrict__ Btw,
    const float* __restrict__ bias, void* Cout, int N, int relu) {
    extern __shared__ uint32_t sm[];
    const int tid = threadIdx.x;
    const int lane = tid & 31, wid = tid >> 5;
    const int gid = lane >> 2, tig = lane & 3;
    const int wm = wid >> 1, wn = wid & 1;
    const int row = tid >> 1, ah = tid & 1;

    const char* brp = (const char*)Btw + (size_t)(n0 + row) * 1024 + ah * 16;

    uint32_t su = smem_u32(sm);
    uint32_t bdst[4];
#pragma unroll
    for (int q = 0; q < 4; q++)
        bdst[q] = su + (uint32_t)(2048 + q * 1024 + row * 8 + ah * 4) * 4;

    float acc[2][8][4];
#pragma unroll
    for (int mi = 0; mi < 2; mi++)
#pragma unroll
        for (int ni = 0; ni < 8; ni++)
#pragma unroll
            for (int q = 0; q < 4; q++) acc[mi][ni][q] = 0.f;

    float4 pa1[2];
    uint4 ua1, ua2;

#define LDA(s) do {                                                           \
    if (MODE == 2) {                                                          \
        ua1 = arpA[(s) * 2 + ah];                                             \
        ua2 = arpB[(s) * 2 + ah];                                             \
    } else {                                                                  \
        int _k = (s) * 16;                                                    \
        pa1[0] = *(const float4*)(arpF + _k);                                 \
        pa1[1] = *(const float4*)(arpF + _k + 8);                             \
    } } while (0)

#define STA(b) do {                                                           \
    uint4 q;                                                                  \
    if (MODE == 2) {                                                          \
        q.x = addrelu_bf2(ua1.x, ua2.x);                                      \
        q.y = addrelu_bf2(ua1.y, ua2.y);                                      \
        q.z = addrelu_bf2(ua1.z, ua2.z);                                      \
        q.w = addrelu_bf2(ua1.w, ua2.w);                                      \
    } else {                                                                  \
        q = make_uint4(packbf(pa1[0].x, pa1[0].y), packbf(pa1[1].x, pa1[1].y),\
                       packbf(pa1[0].z, pa1[0].w), packbf(pa1[1].z, pa1[1].w));\
    }                                                                         \
    *(uint4*)&sm[(b) * 1024 + row * 8 + ah * 4] = q; } while (0)

#define LDB(s, q) do { if ((s) < 32)                                          \
        CP_ASYNC16(bdst[q], brp + (s) * 32);                                  \
    CP_COMMIT(); } while (0)

#define COMPUTE(AB, BB) do {                                                  \
    const uint32_t* A_ = sm + (AB) * 1024;                                    \
    const uint32_t* B_ = sm + 2048 + (BB) * 1024;                             \
    uint2 bfr[8];                                                             \
    _Pragma("unroll") for (int ni = 0; ni < 8; ni++) {                        \
        int nr = wn * 64 + ni * 8 + gid;                                      \
        bfr[ni] = *(const uint2*)&B_[nr * 8 + tig * 2];                       \
    }                                                                         \
    _Pragma("unroll") for (int mi = 0; mi < 2; mi++) {                        \
        int r = wm * 32 + mi * 16 + gid;                                      \
        uint2 u0 = *(const uint2*)&A_[r * 8 + tig * 2];                       \
        uint2 u1 = *(const uint2*)&A_[(r + 8) * 8 + tig * 2];                 \
        _Pragma("unroll") for (int ni = 0; ni < 8; ni++)                      \
            mma_bf16(acc[mi][ni], u0.x, u1.x, u0.y, u1.y,                     \
                     bfr[ni].x, bfr[ni].y);                                   \
    } } while (0)

#define ITER(s, AB, BB) do {                                                  \
    if ((s) + 1 < 32) STA((AB) ^ 1);                                          \
    if ((s) + 2 < 32) LDA((s) + 2);                                           \
    LDB((s) + 3, ((BB) + 3) & 3);                                             \
    CP_WAIT(2);                                                               \
    COMPUTE(AB, BB);                                                          \
    __syncthreads(); } while (0)

    LDA(0); STA(0);
    LDB(0, 0); LDB(1, 1); LDB(2, 2);
    LDA(1);
    CP_WAIT(2);
    __syncthreads();

#pragma unroll 1
    for (int s0 = 0; s0 < 28; s0 += 4) {
        ITER(s0 + 0, 0, 0);
        ITER(s0 + 1, 1, 1);
        ITER(s0 + 2, 0, 2);
        ITER(s0 + 3, 1, 3);
    }
    ITER(28, 0, 0);
    ITER(29, 1, 1);
    ITER(30, 0, 2);
    ITER(31, 1, 3);

#undef LDA
#undef STA
#undef LDB
#undef COMPUTE
#undef ITER

    if (MODE == 2) {
        float* sred = (float*)(sm + 6144);
#pragma unroll
        for (int mi = 0; mi < 2; mi++) {
            float p0 = 0.f, p1 = 0.f;
#pragma unroll
            for (int ni = 0; ni < 8; ni++) {
                int nn = n0 + wn * 64 + ni * 8 + 2 * tig;
                float b2a = g_b2p[nn],     w3a = g_w3p[nn];
                float b2b = g_b2p[nn + 1], w3b = g_w3p[nn + 1];
                p0 += fmaxf(acc[mi][ni][0] + b2a, 0.f) * w3a
                    + fmaxf(acc[mi][ni][1] + b2b, 0.f) * w3b;
                p1 += fmaxf(acc[mi][ni][2] + b2a, 0.f) * w3a
                    + fmaxf(acc[mi][ni][3] + b2b, 0.f) * w3b;
            }
            p0 += __shfl_xor_sync(0xFFFFFFFFu, p0, 1);
            p0 += __shfl_xor_sync(0xFFFFFFFFu, p0, 2);
            p1 += __shfl_xor_sync(0xFFFFFFFFu, p1, 1);
            p1 += __shfl_xor_sync(0xFFFFFFFFu, p1, 2);
            if (tig == 0) {
                int r = wm * 32 + mi * 16 + gid;
                sred[r * 2 + wn] = p0;
                sred[(r + 8) * 2 + wn] = p1;
            }
        }
        __syncthreads();
        if (tid < 128)
            g_scpart[blockIdx.x * NPAIR + m0 + tid] = sred[tid * 2] + sred[tid * 2 + 1];
    } else if (MODE == 1) {
        uint32_t* Cw = (uint32_t*)Cout;
#pragma unroll
        for (int mi = 0; mi < 2; mi++) {
            int r = m0 + wm * 32 + mi * 16 + gid;
#pragma unroll
            for (int ni = 0; ni < 8; ni++) {
                int nn = n0 + wn * 64 + ni * 8 + 2 * tig;
                float ba = (bias && nn < N) ? bias[nn] : 0.f;
                float bb = (bias && nn + 1 < N) ? bias[nn + 1] : 0.f;
                float c0 = (nn < N) ? acc[mi][ni][0] + ba : 0.f;
                float c1 = (nn + 1 < N) ? acc[mi][ni][1] + bb : 0.f;
                float c2 = (nn < N) ? acc[mi][ni][2] + ba : 0.f;
                float c3 = (nn + 1 < N) ? acc[mi][ni][3] + bb : 0.f;
                int g = nn >> 1;
                int pos = (g & ~7) + PERMW(g & 7);
                Cw[(size_t)r * 256 + pos] = packbf(c0, c1);
                Cw[(size_t)(r + 8) * 256 + pos] = packbf(c2, c3);
            }
        }
    } else {
        float* C = (float*)Cout;
#pragma unroll
        for (int mi = 0; mi < 2; mi++) {
            int r = m0 + wm * 32 + mi * 16 + gid;
#pragma unroll
            for (int ni = 0; ni < 8; ni++) {
                int nn = n0 + wn * 64 + ni * 8 + 2 * tig;
                float ba = (bias && nn < N) ? bias[nn] : 0.f;
                float bb = (bias && nn + 1 < N) ? bias[nn + 1] : 0.f;
                float c0 = (nn < N) ? acc[mi][ni][0] + ba : 0.f;
                float c1 = (nn + 1 < N) ? acc[mi][ni][1] + bb : 0.f;
                float c2 = (nn < N) ? acc[mi][ni][2] + ba : 0.f;
                float c3 = (nn + 1 < N) ? acc[mi][ni][3] + bb : 0.f;
                if (relu) {
                    c0 = fmaxf(c0, 0.f); c1 = fmaxf(c1, 0.f);
                    c2 = fmaxf(c2, 0.f); c3 = fmaxf(c3, 0.f);
                }
                *(float2*)&C[(size_t)r * DMODEL + nn] = make_float2(c0, c1);
                *(float2*)&C[(size_t)(r + 8) * DMODEL + nn] = make_float2(c2, c3);
            }
        }
    }
}

// ---------------- kernel wrappers (R13 structure) ----------------
__global__ void __launch_bounds__(256, 2) pair_mma_kernel(const int* __restrict__ s2c) {
    const int m0 = blockIdx.y * 128;
    const int row = threadIdx.x >> 1;
    int p = m0 + row, nsp = p / 65, l = p - nsp * 65;
    const uint4* a1 = (const uint4*)(g_span_b + (size_t)nsp * 256);
    const uint4* a2 = (l < LMAX)
        ? (const uint4*)(g_know_b + (size_t)s2c[nsp * LMAX + l] * 256)
        : (const uint4*)(g_sent_b + (size_t)nsp * 256);
    gemm_core<2>(m0, blockIdx.x * 128, nullptr, a1, a2, g_W2b,
                 nullptr, nullptr, 0, 0);
}

// sentinel(z0) / span_part(z1) / know_part(z2) / sent_part(z3, waits on z0)
__global__ void __launch_bounds__(256, 2) small_multi_kernel(
    const float* __restrict__ span, const float* __restrict__ know,
    const float* __restrict__ bs, const float* __restrict__ b1) {
    int z = blockIdx.z;
    if (z != 2 && blockIdx.y >= 2) return;
    const int m0 = blockIdx.y * 128;
    const int n0 = blockIdx.x * 128;
    const int row = threadIdx.x >> 1, ah = threadIdx.x & 1;
    if (z == 0) {
        const float* a = span + (size_t)(m0 + row) * DMODEL + ah * 4;
        gemm_core<0>(m0, n0, a, nullptr, nullptr, g_Wsb, bs, g_sentinel, DMODEL, 1);
        __syncthreads();
        if (threadIdx.x == 0) { __threadfence(); atomicAdd(&g_sentflag, 1); }
    } else if (z == 1) {
        const float* a = span + (size_t)(m0 + row) * DMODEL + ah * 4;
        gemm_core<1>(m0, n0, a, nullptr, nullptr, g_W1ab, b1, g_span_b, HID, 0);
    } else if (z == 2) {
        const float* a = know + (size_t)(m0 + row) * DMODEL + ah * 4;
        gemm_core<1>(m0, n0, a, nullptr, nullptr, g_W1bb, nullptr, g_know_b, HID, 0);
    } else {
        if (threadIdx.x == 0) {
            while (atomicAdd(&g_sentflag, 0) < 8) __nanosleep(64);
        }
        __syncthreads();
        const float* a = g_sentinel + (size_t)(m0 + row) * DMODEL + ah * 4;
        gemm_core<1>(m0, n0, a, nullptr, nullptr, g_W1bb, nullptr, g_sent_b, HID, 0);
    }
}

// ---------------- softmax + features (R13 v2: 256 thr, shfl red) -----------
__global__ void __launch_bounds__(256) softmax_features_kernel(
    const int* __restrict__ s2c, const int* __restrict__ lengths,
    const float* __restrict__ know, float* __restrict__ out) {
    int n = blockIdx.x;
    int t = threadIdx.x;
    __shared__ float sc[65];
    __shared__ const float* eptr[65];
    __shared__ float rmax, rinv;

    if (t < 65) {
        float s = 0.f;
#pragma unroll
        for (int q = 0; q < 4; q++) s += g_scpart[q * NPAIR + n * 65 + t];
        bool valid;
        const float* ep;
        if (t < LMAX) {
            int len = lengths[n];
            if (len < 1) len = 1;
            valid = t < len;
            ep = know + (size_t)s2c[n * LMAX + t] * DMODEL;
        } else {
            valid = true;
            ep = g_sentinel + (size_t)n * DMODEL;
        }
        sc[t] = valid ? s : -1e30f;
        eptr[t] = ep;
    }
    __syncthreads();
    if (t < 32) {
        float v = fmaxf(sc[t], sc[t + 32]);
        if (t == 0) v = fmaxf(v, sc[64]);
#pragma unroll
        for (int o = 16; o; o >>= 1)
            v = fmaxf(v, __shfl_xor_sync(0xFFFFFFFFu, v, o));
        if (t == 0) rmax = v;
    }
    __syncthreads();
    float m = rmax;
    if (t < 65) sc[t] = expf(sc[t] - m);
    __syncthreads();
    if (t < 32) {
        float v = sc[t] + sc[t + 32];
        if (t == 0) v += sc[64];
#pragma unroll
        for (int o = 16; o; o >>= 1)
            v += __shfl_xor_sync(0xFFFFFFFFu, v, o);
        if (t == 0) rinv = 1.f / v;
    }
    __syncthreads();
    float inv = rinv;
    if (t < 65) {
        sc[t] *= inv;
        out[NSPAN * DMODEL + n * 65 + t] = sc[t];   // probs
    }
    __syncthreads();
    // features: each thread owns 2 consecutive dims (float2, coalesced)
    float a0 = 0.f, a1 = 0.f;
#pragma unroll 5
    for (int l = 0; l < 65; l++) {
        float pr = sc[l];
        float2 e = *(const float2*)&eptr[l][2 * t];
        a0 += pr * e.x;
        a1 += pr * e.y;
    }
    *(float2*)&out[n * DMODEL + 2 * t] = make_float2(a0, a1);
}

// ---------------- launch ----------------
extern "C" void kernel_launch(void* const* d_in, const int* in_sizes, int n_in,
                              void* d_out, int out_size) {
    const float* span    = (const float*)d_in[0];
    const float* know    = (const float*)d_in[1];
    const int*   s2c     = (const int*)d_in[2];
    const int*   lengths = (const int*)d_in[3];
    const float* Ws      = (const float*)d_in[4];
    const float* bs      = (const float*)d_in[5];
    const float* W1      = (const float*)d_in[6];
    const float* b1      = (const float*)d_in[7];
    const float* W2      = (const float*)d_in[8];
    const float* b2      = (const float*)d_in[9];
    const float* W3      = (const float*)d_in[10];
    // d_in[11] = b3: softmax-invariant constant shift, intentionally unused.
    float* out = (float*)d_out;

    cudaFuncSetAttribute(small_multi_kernel,
                         cudaFuncAttributeMaxDynamicSharedMemorySize, SMEM_BYTES);
    cudaFuncSetAttribute(pair_mma_kernel,
                         cudaFuncAttributeMaxDynamicSharedMemorySize, SMEM_BYTES);

    // weights -> bf16x2 permuted (high-parallelism transpose); pad b2/w3
    prep_kernel<<<dim3(128, 4), 256>>>(W2, Ws, W1, b2, W3);
    // sentinel / span_part / know_part / sent_part in ONE launch
    small_multi_kernel<<<dim3(4, 8, 4), 256, SMEM_BYTES>>>(span, know, bs, b1);
    // fused h1 -> h2 -> score partials (bf16, packed-part A)
    pair_mma_kernel<<<dim3(4, 130), 256, SMEM_BYTES>>>(s2c);
    // softmax + features
    softmax_features_kernel<<<NSPAN, 256>>>(s2c, lengths, know, out);
}